// round 12
// baseline (speedup 1.0000x reference)
#include <cuda_runtime.h>
#include <cuda_fp16.h>
#include <stdint.h>
#include <math.h>

#define DD 512
#define BATCH 8
#define SEQ 2048
#define MTOT (BATCH * SEQ)   // 16384

#define TM 128
#define TN 128
#define BKK 64
#define NTH 128              // 4 warps: 2m x 2n, warp tile 64x64

#define STG_BYTES 32768
#define NSTG 3
#define SMEM_TOTAL (NSTG * STG_BYTES)   // 98304; 2 CTAs/SM

// scale(1/sqrt(512)) * log2(e): Q pre-scaled so SC acc is log2 of exp argument
#define QSCALE 0.06375871588f

// ---------------- scratch (device globals; no allocation) ----------------
__device__ __align__(1024) __half g_ITh[MTOT * DD];
__device__ __align__(1024) __half g_ISh[MTOT * DD];
__device__ __align__(1024) __half g_Wh[12 * DD * DD];                     // [Q0..3|K0..3|V0..3]
__device__ __align__(1024) __half g_Qh[4 * MTOT * DD];
__device__ __align__(1024) __half g_Kh[4 * MTOT * DD];
__device__ __align__(1024) __half g_Vth[4 * DD * MTOT];                   // [blk][feat][tok]
__device__ __align__(1024) __half g_S[(size_t)32 * SEQ * SEQ];            // unnormalized exp
__device__ __align__(1024) float  g_RS[32 * SEQ];                         // row sums
__device__ __align__(1024) __half g_Ah[MTOT * DD];                        // FTT+FTS (RED target)
__device__ __align__(1024) __half g_Ch[MTOT * DD];                        // FSS+FST (RED target)

// ---------------- helpers ----------------
__device__ __forceinline__ uint32_t s2u(const void* p) {
    uint32_t a;
    asm("{ .reg .u64 t; cvta.to.shared.u64 t, %1; cvt.u32.u64 %0, t; }" : "=r"(a) : "l"(p));
    return a;
}
__device__ __forceinline__ void cp16(uint32_t dst, const void* src) {
    asm volatile("cp.async.cg.shared.global [%0], [%1], 16;" :: "r"(dst), "l"(src));
}
__device__ __forceinline__ void cp_commit() { asm volatile("cp.async.commit_group;" ::: "memory"); }
template <int N> __device__ __forceinline__ void cp_wait() {
    asm volatile("cp.async.wait_group %0;" :: "n"(N) : "memory");
}
__device__ __forceinline__ void ldsm4(uint32_t* d, uint32_t addr) {
    asm volatile("ldmatrix.sync.aligned.m8n8.x4.shared.b16 {%0,%1,%2,%3}, [%4];"
                 : "=r"(d[0]), "=r"(d[1]), "=r"(d[2]), "=r"(d[3]) : "r"(addr));
}
__device__ __forceinline__ void mma16816(float* c, const uint32_t* a, uint32_t b0, uint32_t b1) {
    asm volatile(
        "mma.sync.aligned.m16n8k16.row.col.f32.f16.f16.f32 "
        "{%0,%1,%2,%3},{%4,%5,%6,%7},{%8,%9},{%0,%1,%2,%3};"
        : "+f"(c[0]), "+f"(c[1]), "+f"(c[2]), "+f"(c[3])
        : "r"(a[0]), "r"(a[1]), "r"(a[2]), "r"(a[3]), "r"(b0), "r"(b1));
}

// =============== shared mainloop (CTA 128x128, 4 warps, 64x64 warp tile) ====
#define GEMM_MAINLOOP(Ap, Bp, ldA, ldB, K)                                        \
    float acc[4][8][4];                                                           \
    _Pragma("unroll")                                                             \
    for (int i = 0; i < 4; i++)                                                   \
        _Pragma("unroll")                                                         \
        for (int j = 0; j < 8; j++)                                               \
            _Pragma("unroll")                                                     \
            for (int e = 0; e < 4; e++) acc[i][j][e] = 0.f;                       \
    const int nK = (K) / BKK;                                                     \
    auto load_stage = [&](int ck, int stg) {                                      \
        const int k0 = ck * BKK;                                                  \
        const uint32_t sb = sbase + stg * STG_BYTES;                              \
        _Pragma("unroll")                                                         \
        for (int t = 0; t < 8; t++) {                                             \
            int id = tid + t * NTH;                                               \
            int r = id >> 3, c = id & 7;                                          \
            cp16(sb + r * 128 + (((c ^ (r & 7)) & 7) << 4),                       \
                 (Ap) + (size_t)(m0 + r) * (ldA) + k0 + c * 8);                   \
        }                                                                         \
        _Pragma("unroll")                                                         \
        for (int t = 0; t < 8; t++) {                                             \
            int id = tid + t * NTH;                                               \
            int r = id >> 3, c = id & 7;                                          \
            cp16(sb + 16384 + r * 128 + (((c ^ (r & 7)) & 7) << 4),               \
                 (Bp) + (size_t)(n0 + r) * (ldB) + k0 + c * 8);                   \
        }                                                                         \
        cp_commit();                                                              \
    };                                                                            \
    load_stage(0, 0);                                                             \
    if (nK > 1) load_stage(1, 1);                                                 \
    for (int i = 0; i < nK; i++) {                                                \
        if (i + 1 < nK) cp_wait<1>(); else cp_wait<0>();                          \
        __syncthreads();                                                          \
        if (i + 2 < nK) load_stage(i + 2, (i + 2) % 3);                           \
        const uint32_t sA = sbase + (i % 3) * STG_BYTES;                          \
        const uint32_t sB = sA + 16384;                                           \
        _Pragma("unroll")                                                         \
        for (int s = 0; s < 4; s++) {                                             \
            uint32_t af[4][4];                                                    \
            _Pragma("unroll")                                                     \
            for (int im = 0; im < 4; im++) {                                      \
                int row = wm * 64 + im * 16 + (lane & 15);                        \
                int ch  = 2 * s + (lane >> 4);                                    \
                ldsm4(af[im], sA + row * 128 + (((ch ^ (row & 7)) & 7) << 4));    \
            }                                                                     \
            uint32_t bf[4][4];                                                    \
            _Pragma("unroll")                                                     \
            for (int j2 = 0; j2 < 4; j2++) {                                      \
                int row = wn * 64 + j2 * 16 + ((lane >> 4) << 3) + (lane & 7);    \
                int ch  = 2 * s + ((lane >> 3) & 1);                              \
                ldsm4(bf[j2], sB + row * 128 + (((ch ^ (row & 7)) & 7) << 4));    \
            }                                                                     \
            _Pragma("unroll")                                                     \
            for (int im = 0; im < 4; im++)                                        \
                _Pragma("unroll")                                                 \
                for (int jn = 0; jn < 8; jn++)                                    \
                    mma16816(acc[im][jn], af[im], bf[jn >> 1][(jn & 1) * 2],      \
                             bf[jn >> 1][(jn & 1) * 2 + 1]);                      \
        }                                                                         \
    }

// ---------------------------------------------------------------------------
// Merged projection kernel: z = proj*4 + blk  (proj: 0=Q, 1=K, 2=V)
// Q output is pre-scaled by QSCALE so scores acc = log2(exp argument).
// ---------------------------------------------------------------------------
__global__ __launch_bounds__(NTH, 2)
void proj_kernel(const __half* __restrict__ IT, const __half* __restrict__ IS,
                 const __half* __restrict__ Wall,
                 const float* __restrict__ bq, const float* __restrict__ bk,
                 const float* __restrict__ bv,
                 __half* __restrict__ Qh, __half* __restrict__ Kh,
                 __half* __restrict__ Vth)
{
    extern __shared__ __align__(16) char smem[];
    const uint32_t sbase = s2u(smem);
    const int tid  = threadIdx.x;
    const int lane = tid & 31;
    const int warp = tid >> 5;
    const int wm = warp & 1;
    const int wn = warp >> 1;
    const int z  = blockIdx.z;
    const int proj = z >> 2;
    const int blk  = z & 3;
    const int m0 = blockIdx.y * TM;
    const int n0 = blockIdx.x * TN;
    const long long sBUF = (long long)MTOT * DD;

    const __half* Ap = (((0x66Au >> z) & 1) ? IS : IT);
    const __half* Bp = Wall + (size_t)z * DD * DD;
    const float*  Xp = (proj == 0 ? bq : proj == 1 ? bk : bv) + blk * DD;

    GEMM_MAINLOOP(Ap, Bp, DD, DD, DD)

    const int lm = lane >> 2;
    const int ln = (lane & 3) * 2;

    if (proj == 2) {
        __syncthreads();
        __half* st = (__half*)smem;
        #pragma unroll
        for (int im = 0; im < 4; im++) {
            int ml = wm * 64 + im * 16 + lm;
            #pragma unroll
            for (int jn = 0; jn < 8; jn++) {
                int nl = wn * 64 + jn * 8 + ln;
                float b0 = Xp[n0 + nl], b1 = Xp[n0 + nl + 1];
                st[nl * 136 + ml]           = __float2half(acc[im][jn][0] + b0);
                st[(nl + 1) * 136 + ml]     = __float2half(acc[im][jn][1] + b1);
                st[nl * 136 + ml + 8]       = __float2half(acc[im][jn][2] + b0);
                st[(nl + 1) * 136 + ml + 8] = __float2half(acc[im][jn][3] + b1);
            }
        }
        __syncthreads();
        __half* O = Vth + (size_t)blk * sBUF;
        #pragma unroll
        for (int t = 0; t < 16; t++) {
            int idx = tid + t * NTH;
            int r = idx >> 4, sgl = idx & 15;
            uint4 v = *(const uint4*)(st + r * 136 + sgl * 8);
            *(uint4*)(O + (size_t)(n0 + r) * MTOT + m0 + sgl * 8) = v;
        }
        return;
    }

    const float qs = (proj == 0) ? QSCALE : 1.0f;
    __half* O = (proj == 0 ? Qh : Kh) + (size_t)blk * sBUF;
    #pragma unroll
    for (int im = 0; im < 4; im++) {
        int r0 = m0 + wm * 64 + im * 16 + lm;
        int r1 = r0 + 8;
        #pragma unroll
        for (int jn = 0; jn < 8; jn++) {
            int c = n0 + wn * 64 + jn * 8 + ln;
            float b0 = Xp[c], b1 = Xp[c + 1];
            *(__half2*)(O + (size_t)r0 * DD + c) =
                __floats2half2_rn((acc[im][jn][0] + b0) * qs, (acc[im][jn][1] + b1) * qs);
            *(__half2*)(O + (size_t)r1 * DD + c) =
                __floats2half2_rn((acc[im][jn][2] + b0) * qs, (acc[im][jn][3] + b1) * qs);
        }
    }
}

// ---------------------------------------------------------------------------
// Generic NT GEMM (scores / PV / final), z-batched
// MODE_SC: P = exp2(acc) via h2exp2 (Q pre-scaled), rowsum atomics into RS
// MODE_PV: multiplies by 1/RS[row], REDs fp16x2 into Ah (blk 0,2) / Ch (1,3)
// ---------------------------------------------------------------------------
enum { MODE_SC = 2, MODE_PV = 3, MODE_FIN = 4 };

template <int MODE>
__global__ __launch_bounds__(NTH, 2)
void hgemm(const __half* __restrict__ A0, const __half* __restrict__ B,
           void* __restrict__ out, void* __restrict__ out2,
           const float* __restrict__ X, float* __restrict__ RS,
           int ldA, int ldB, int ldC, int K,
           long long sAhi, long long sAlo, long long sBhi, long long sBlo,
           long long sChi, long long sClo, long long sXlo)
{
    extern __shared__ __align__(16) char smem[];
    const uint32_t sbase = s2u(smem);
    const int tid  = threadIdx.x;
    const int lane = tid & 31;
    const int warp = tid >> 5;
    const int wm = warp & 1;
    const int wn = warp >> 1;
    const int z  = blockIdx.z;
    const int zh = z >> 3, zl = z & 7;
    const int m0 = blockIdx.y * TM;
    const int n0 = blockIdx.x * TN;

    const __half* Ap = A0 + zh * sAhi + zl * sAlo;
    const __half* Bp = B + zh * sBhi + zl * sBlo;

    GEMM_MAINLOOP(Ap, Bp, ldA, ldB, K)

    const int lm = lane >> 2;
    const int ln = (lane & 3) * 2;

    // output base
    __half* Oh;
    float*  Of;
    if (MODE == MODE_PV) {
        Oh = ((zh & 1) ? (__half*)out2 : (__half*)out) + (size_t)zl * sClo;
    } else if (MODE == MODE_SC) {
        Oh = (__half*)out + (size_t)(zh * sChi + zl * sClo);
    } else {
        Of = (float*)out + (size_t)(zh * sChi + zl * sClo);
    }

    const __half2 clamp15 = __float2half2_rn(15.f);

    #pragma unroll
    for (int im = 0; im < 4; im++) {
        int r0 = m0 + wm * 64 + im * 16 + lm;
        int r1 = r0 + 8;
        float s0 = 0.f, s1 = 0.f;
        float inv0, inv1;
        if (MODE == MODE_PV) {
            inv0 = 1.0f / RS[(size_t)z * SEQ + r0];
            inv1 = 1.0f / RS[(size_t)z * SEQ + r1];
        }
        #pragma unroll
        for (int jn = 0; jn < 8; jn++) {
            int c = n0 + wn * 64 + jn * 8 + ln;
            float v0 = acc[im][jn][0], v1 = acc[im][jn][1];
            float v2 = acc[im][jn][2], v3 = acc[im][jn][3];
            if (MODE == MODE_SC) {
                __half2 p01 = h2exp2(__hmin2(__floats2half2_rn(v0, v1), clamp15));
                __half2 p23 = h2exp2(__hmin2(__floats2half2_rn(v2, v3), clamp15));
                *(__half2*)(Oh + (size_t)r0 * ldC + c) = p01;
                *(__half2*)(Oh + (size_t)r1 * ldC + c) = p23;
                float2 f0 = __half22float2(p01), f1 = __half22float2(p23);
                s0 += f0.x + f0.y;
                s1 += f1.x + f1.y;
            } else if (MODE == MODE_PV) {
                atomicAdd((__half2*)(Oh + (size_t)r0 * ldC + c),
                          __floats2half2_rn(v0 * inv0, v1 * inv0));
                atomicAdd((__half2*)(Oh + (size_t)r1 * ldC + c),
                          __floats2half2_rn(v2 * inv1, v3 * inv1));
            } else {  // MODE_FIN
                const float* Xz = X + zl * sXlo;
                size_t o0 = (size_t)r0 * ldC + c, o1 = (size_t)r1 * ldC + c;
                float2 p0 = *(const float2*)(Xz + o0), p1 = *(const float2*)(Xz + o1);
                *(float2*)(Of + o0) = make_float2(v0 + p0.x, v1 + p0.y);
                *(float2*)(Of + o1) = make_float2(v2 + p1.x, v3 + p1.y);
            }
        }
        if (MODE == MODE_SC) {
            s0 += __shfl_xor_sync(0xffffffffu, s0, 1);
            s0 += __shfl_xor_sync(0xffffffffu, s0, 2);
            s1 += __shfl_xor_sync(0xffffffffu, s1, 1);
            s1 += __shfl_xor_sync(0xffffffffu, s1, 2);
            if ((lane & 3) == 0) {
                atomicAdd(RS + (size_t)z * SEQ + r0, s0);
                atomicAdd(RS + (size_t)z * SEQ + r1, s1);
            }
        }
    }
}

// ---------------------------------------------------------------------------
// Fused fp32 -> fp16 convert of all 5 inputs + zero RS, Ah, Ch
// ---------------------------------------------------------------------------
#define N4_IN (MTOT * DD / 4)        // 2097152
#define N4_W  (4 * DD * DD / 4)      // 262144
#define N4_RS (32 * SEQ / 4)         // 16384
#define N16_AC (MTOT * DD / 8)       // 1048576 uint4 units per fp16 buffer
#define ZBASE (2 * N4_IN + 3 * N4_W)
__global__ __launch_bounds__(256)
void convert_all(const float* __restrict__ IT, const float* __restrict__ IS,
                 const float* __restrict__ Wq, const float* __restrict__ Wk,
                 const float* __restrict__ Wv,
                 __half* __restrict__ oIT, __half* __restrict__ oIS,
                 __half* __restrict__ oWq, __half* __restrict__ oWk,
                 __half* __restrict__ oWv, float* __restrict__ RS,
                 __half* __restrict__ Ah, __half* __restrict__ Ch)
{
    const int total = ZBASE + N4_RS + 2 * N16_AC;
    int idx = blockIdx.x * blockDim.x + threadIdx.x;
    int stride = gridDim.x * blockDim.x;
    const uint4 zu = make_uint4(0u, 0u, 0u, 0u);
    for (int i = idx; i < total; i += stride) {
        if (i >= ZBASE) {
            int j = i - ZBASE;
            if (j < N4_RS)            ((uint4*)RS)[j] = zu;
            else if ((j -= N4_RS) < N16_AC) ((uint4*)Ah)[j] = zu;
            else                      ((uint4*)Ch)[j - N16_AC] = zu;
            continue;
        }
        const float4* s; __half2* d; int off;
        if (i < N4_IN)                     { s = (const float4*)IT; d = (__half2*)oIT; off = i; }
        else if (i < 2 * N4_IN)            { s = (const float4*)IS; d = (__half2*)oIS; off = i - N4_IN; }
        else if (i < 2 * N4_IN + N4_W)     { s = (const float4*)Wq; d = (__half2*)oWq; off = i - 2 * N4_IN; }
        else if (i < 2 * N4_IN + 2 * N4_W) { s = (const float4*)Wk; d = (__half2*)oWk; off = i - 2 * N4_IN - N4_W; }
        else                               { s = (const float4*)Wv; d = (__half2*)oWv; off = i - 2 * N4_IN - 2 * N4_W; }
        float4 v = s[off];
        d[off * 2]     = __floats2half2_rn(v.x, v.y);
        d[off * 2 + 1] = __floats2half2_rn(v.z, v.w);
    }
}

// ---------------------------------------------------------------------------
extern "C" void kernel_launch(void* const* d_in, const int* in_sizes, int n_in,
                              void* d_out, int out_size)
{
    const float* Itime   = (const float*)d_in[0];
    const float* Ispace  = (const float*)d_in[1];
    const float* xorigin = (const float*)d_in[2];
    const float* Wq      = (const float*)d_in[3];
    const float* bq      = (const float*)d_in[4];
    const float* Wk      = (const float*)d_in[5];
    const float* bk      = (const float*)d_in[6];
    const float* Wv      = (const float*)d_in[7];
    const float* bv      = (const float*)d_in[8];
    float* out = (float*)d_out;

    __half *ITh, *ISh, *Wh, *Qh, *Kh, *Vth, *Sh, *Ah, *Ch;
    float *RS;
    cudaGetSymbolAddress((void**)&ITh, g_ITh);
    cudaGetSymbolAddress((void**)&ISh, g_ISh);
    cudaGetSymbolAddress((void**)&Wh,  g_Wh);
    cudaGetSymbolAddress((void**)&Qh,  g_Qh);
    cudaGetSymbolAddress((void**)&Kh,  g_Kh);
    cudaGetSymbolAddress((void**)&Vth, g_Vth);
    cudaGetSymbolAddress((void**)&Sh,  g_S);
    cudaGetSymbolAddress((void**)&RS,  g_RS);
    cudaGetSymbolAddress((void**)&Ah,  g_Ah);
    cudaGetSymbolAddress((void**)&Ch,  g_Ch);

    cudaFuncSetAttribute(proj_kernel,     cudaFuncAttributeMaxDynamicSharedMemorySize, SMEM_TOTAL);
    cudaFuncSetAttribute(hgemm<MODE_SC>,  cudaFuncAttributeMaxDynamicSharedMemorySize, SMEM_TOTAL);
    cudaFuncSetAttribute(hgemm<MODE_PV>,  cudaFuncAttributeMaxDynamicSharedMemorySize, SMEM_TOTAL);
    cudaFuncSetAttribute(hgemm<MODE_FIN>, cudaFuncAttributeMaxDynamicSharedMemorySize, SMEM_TOTAL);

    const long long sQKV = (long long)SEQ * DD;
    const long long sBUF = (long long)MTOT * DD;
    const long long sS   = (long long)SEQ * SEQ;

    convert_all<<<4096, 256>>>(Itime, Ispace, Wq, Wk, Wv,
                               ITh, ISh, Wh, Wh + 4 * DD * DD, Wh + 8 * DD * DD,
                               RS, Ah, Ch);

    dim3 gproj(DD / TN, MTOT / TM, 12);
    proj_kernel<<<gproj, NTH, SMEM_TOTAL>>>(ITh, ISh, Wh, bq, bk, bv, Qh, Kh, Vth);

    // Scores + exp2 + rowsum atomics (Q pre-scaled; normalization deferred)
    dim3 gsc(SEQ / TN, SEQ / TM, 32);
    hgemm<MODE_SC><<<gsc, NTH, SMEM_TOTAL>>>(
        Qh, Kh, Sh, nullptr, nullptr, RS,
        DD, DD, SEQ, DD,
        8 * sQKV, sQKV, 8 * sQKV, sQKV, 8 * sS, sS, 0);

    // PV: normalize + RED fp16x2 into Ah (blk 0,2) / Ch (blk 1,3)
    dim3 gpv(DD / TN, SEQ / TM, 32);
    hgemm<MODE_PV><<<gpv, NTH, SMEM_TOTAL>>>(
        Sh, Vth, Ah, Ch, nullptr, RS,
        SEQ, MTOT, DD, SEQ,
        8 * sS, sS, sBUF, SEQ, 0, sQKV, 0);

    // out[z] = A[z] @ C[z]^T + x_origin[z]
    dim3 gfin(SEQ / TN, SEQ / TM, BATCH);
    hgemm<MODE_FIN><<<gfin, NTH, SMEM_TOTAL>>>(
        Ah, Ch, out, nullptr, xorigin, nullptr,
        DD, DD, SEQ, DD,
        0, sQKV, 0, sQKV, 0, sS, sS);
}

// round 13
// speedup vs baseline: 1.0075x; 1.0075x over previous
#include <cuda_runtime.h>
#include <cuda_fp16.h>
#include <stdint.h>
#include <math.h>

#define DD 512
#define BATCH 8
#define SEQ 2048
#define MTOT (BATCH * SEQ)   // 16384

#define TM 128
#define TN 128
#define BKK 64
#define NTH 128              // 4 warps: 2m x 2n, warp tile 64x64

#define STG_BYTES 32768
#define NSTG 3
#define SMEM_TOTAL (NSTG * STG_BYTES)   // 98304; 2 CTAs/SM

// scale(1/sqrt(512)) * log2(e): Q pre-scaled so SC acc is log2 of exp argument
#define QSCALE 0.06375871588f

// ---------------- scratch (device globals; no allocation) ----------------
__device__ __align__(1024) __half g_ITh[MTOT * DD];
__device__ __align__(1024) __half g_ISh[MTOT * DD];
__device__ __align__(1024) __half g_Wh[12 * DD * DD];                     // [Q0..3|K0..3|V0..3]
__device__ __align__(1024) __half g_Qh[4 * MTOT * DD];
__device__ __align__(1024) __half g_Kh[4 * MTOT * DD];
__device__ __align__(1024) __half g_Vth[4 * DD * MTOT];                   // [blk][feat][tok]
__device__ __align__(1024) __half g_S[(size_t)32 * SEQ * SEQ];            // unnormalized exp
__device__ __align__(1024) float  g_RS[32 * SEQ];                         // row sums
__device__ __align__(1024) __half g_F[(size_t)4 * MTOT * DD];
__device__ __align__(1024) __half g_Ah[MTOT * DD];
__device__ __align__(1024) __half g_Ch[MTOT * DD];

// ---------------- helpers ----------------
__device__ __forceinline__ uint32_t s2u(const void* p) {
    uint32_t a;
    asm("{ .reg .u64 t; cvta.to.shared.u64 t, %1; cvt.u32.u64 %0, t; }" : "=r"(a) : "l"(p));
    return a;
}
__device__ __forceinline__ void cp16(uint32_t dst, const void* src) {
    asm volatile("cp.async.cg.shared.global [%0], [%1], 16;" :: "r"(dst), "l"(src));
}
__device__ __forceinline__ void cp_commit() { asm volatile("cp.async.commit_group;" ::: "memory"); }
template <int N> __device__ __forceinline__ void cp_wait() {
    asm volatile("cp.async.wait_group %0;" :: "n"(N) : "memory");
}
__device__ __forceinline__ void ldsm4(uint32_t* d, uint32_t addr) {
    asm volatile("ldmatrix.sync.aligned.m8n8.x4.shared.b16 {%0,%1,%2,%3}, [%4];"
                 : "=r"(d[0]), "=r"(d[1]), "=r"(d[2]), "=r"(d[3]) : "r"(addr));
}
__device__ __forceinline__ void mma16816(float* c, const uint32_t* a, uint32_t b0, uint32_t b1) {
    asm volatile(
        "mma.sync.aligned.m16n8k16.row.col.f32.f16.f16.f32 "
        "{%0,%1,%2,%3},{%4,%5,%6,%7},{%8,%9},{%0,%1,%2,%3};"
        : "+f"(c[0]), "+f"(c[1]), "+f"(c[2]), "+f"(c[3])
        : "r"(a[0]), "r"(a[1]), "r"(a[2]), "r"(a[3]), "r"(b0), "r"(b1));
}

// =============== shared mainloop (CTA 128x128, 4 warps, 64x64 warp tile) ====
#define GEMM_MAINLOOP(Ap, Bp, ldA, ldB, K)                                        \
    float acc[4][8][4];                                                           \
    _Pragma("unroll")                                                             \
    for (int i = 0; i < 4; i++)                                                   \
        _Pragma("unroll")                                                         \
        for (int j = 0; j < 8; j++)                                               \
            _Pragma("unroll")                                                     \
            for (int e = 0; e < 4; e++) acc[i][j][e] = 0.f;                       \
    const int nK = (K) / BKK;                                                     \
    auto load_stage = [&](int ck, int stg) {                                      \
        const int k0 = ck * BKK;                                                  \
        const uint32_t sb = sbase + stg * STG_BYTES;                              \
        _Pragma("unroll")                                                         \
        for (int t = 0; t < 8; t++) {                                             \
            int id = tid + t * NTH;                                               \
            int r = id >> 3, c = id & 7;                                          \
            cp16(sb + r * 128 + (((c ^ (r & 7)) & 7) << 4),                       \
                 (Ap) + (size_t)(m0 + r) * (ldA) + k0 + c * 8);                   \
        }                                                                         \
        _Pragma("unroll")                                                         \
        for (int t = 0; t < 8; t++) {                                             \
            int id = tid + t * NTH;                                               \
            int r = id >> 3, c = id & 7;                                          \
            cp16(sb + 16384 + r * 128 + (((c ^ (r & 7)) & 7) << 4),               \
                 (Bp) + (size_t)(n0 + r) * (ldB) + k0 + c * 8);                   \
        }                                                                         \
        cp_commit();                                                              \
    };                                                                            \
    load_stage(0, 0);                                                             \
    if (nK > 1) load_stage(1, 1);                                                 \
    for (int i = 0; i < nK; i++) {                                                \
        if (i + 1 < nK) cp_wait<1>(); else cp_wait<0>();                          \
        __syncthreads();                                                          \
        if (i + 2 < nK) load_stage(i + 2, (i + 2) % 3);                           \
        const uint32_t sA = sbase + (i % 3) * STG_BYTES;                          \
        const uint32_t sB = sA + 16384;                                           \
        _Pragma("unroll")                                                         \
        for (int s = 0; s < 4; s++) {                                             \
            uint32_t af[4][4];                                                    \
            _Pragma("unroll")                                                     \
            for (int im = 0; im < 4; im++) {                                      \
                int row = wm * 64 + im * 16 + (lane & 15);                        \
                int ch  = 2 * s + (lane >> 4);                                    \
                ldsm4(af[im], sA + row * 128 + (((ch ^ (row & 7)) & 7) << 4));    \
            }                                                                     \
            uint32_t bf[4][4];                                                    \
            _Pragma("unroll")                                                     \
            for (int j2 = 0; j2 < 4; j2++) {                                      \
                int row = wn * 64 + j2 * 16 + ((lane >> 4) << 3) + (lane & 7);    \
                int ch  = 2 * s + ((lane >> 3) & 1);                              \
                ldsm4(bf[j2], sB + row * 128 + (((ch ^ (row & 7)) & 7) << 4));    \
            }                                                                     \
            _Pragma("unroll")                                                     \
            for (int im = 0; im < 4; im++)                                        \
                _Pragma("unroll")                                                 \
                for (int jn = 0; jn < 8; jn++)                                    \
                    mma16816(acc[im][jn], af[im], bf[jn >> 1][(jn & 1) * 2],      \
                             bf[jn >> 1][(jn & 1) * 2 + 1]);                      \
        }                                                                         \
    }

// ---------------------------------------------------------------------------
// Merged projection kernel: z = proj*4 + blk  (proj: 0=Q, 1=K, 2=V)
// Q output is pre-scaled by QSCALE so scores acc = log2(exp argument).
// ---------------------------------------------------------------------------
__global__ __launch_bounds__(NTH, 2)
void proj_kernel(const __half* __restrict__ IT, const __half* __restrict__ IS,
                 const __half* __restrict__ Wall,
                 const float* __restrict__ bq, const float* __restrict__ bk,
                 const float* __restrict__ bv,
                 __half* __restrict__ Qh, __half* __restrict__ Kh,
                 __half* __restrict__ Vth)
{
    extern __shared__ __align__(16) char smem[];
    const uint32_t sbase = s2u(smem);
    const int tid  = threadIdx.x;
    const int lane = tid & 31;
    const int warp = tid >> 5;
    const int wm = warp & 1;
    const int wn = warp >> 1;
    const int z  = blockIdx.z;
    const int proj = z >> 2;
    const int blk  = z & 3;
    const int m0 = blockIdx.y * TM;
    const int n0 = blockIdx.x * TN;
    const long long sBUF = (long long)MTOT * DD;

    const __half* Ap = (((0x66Au >> z) & 1) ? IS : IT);
    const __half* Bp = Wall + (size_t)z * DD * DD;
    const float*  Xp = (proj == 0 ? bq : proj == 1 ? bk : bv) + blk * DD;

    GEMM_MAINLOOP(Ap, Bp, DD, DD, DD)

    const int lm = lane >> 2;
    const int ln = (lane & 3) * 2;

    if (proj == 2) {
        __syncthreads();
        __half* st = (__half*)smem;
        #pragma unroll
        for (int im = 0; im < 4; im++) {
            int ml = wm * 64 + im * 16 + lm;
            #pragma unroll
            for (int jn = 0; jn < 8; jn++) {
                int nl = wn * 64 + jn * 8 + ln;
                float b0 = Xp[n0 + nl], b1 = Xp[n0 + nl + 1];
                st[nl * 136 + ml]           = __float2half(acc[im][jn][0] + b0);
                st[(nl + 1) * 136 + ml]     = __float2half(acc[im][jn][1] + b1);
                st[nl * 136 + ml + 8]       = __float2half(acc[im][jn][2] + b0);
                st[(nl + 1) * 136 + ml + 8] = __float2half(acc[im][jn][3] + b1);
            }
        }
        __syncthreads();
        __half* O = Vth + (size_t)blk * sBUF;
        #pragma unroll
        for (int t = 0; t < 16; t++) {
            int idx = tid + t * NTH;
            int r = idx >> 4, sgl = idx & 15;
            uint4 v = *(const uint4*)(st + r * 136 + sgl * 8);
            *(uint4*)(O + (size_t)(n0 + r) * MTOT + m0 + sgl * 8) = v;
        }
        return;
    }

    const float qs = (proj == 0) ? QSCALE : 1.0f;
    __half* O = (proj == 0 ? Qh : Kh) + (size_t)blk * sBUF;
    #pragma unroll
    for (int im = 0; im < 4; im++) {
        int r0 = m0 + wm * 64 + im * 16 + lm;
        int r1 = r0 + 8;
        #pragma unroll
        for (int jn = 0; jn < 8; jn++) {
            int c = n0 + wn * 64 + jn * 8 + ln;
            float b0 = Xp[c], b1 = Xp[c + 1];
            *(__half2*)(O + (size_t)r0 * DD + c) =
                __floats2half2_rn((acc[im][jn][0] + b0) * qs, (acc[im][jn][1] + b1) * qs);
            *(__half2*)(O + (size_t)r1 * DD + c) =
                __floats2half2_rn((acc[im][jn][2] + b0) * qs, (acc[im][jn][3] + b1) * qs);
        }
    }
}

// ---------------------------------------------------------------------------
// Generic NT GEMM (scores / PV / final), z-batched
// MODE_SC: P = exp2(acc) via h2exp2 (Q pre-scaled), rowsum atomics into RS
// MODE_PV: multiplies by 1/RS[row], plain fp16 stores into F
// ---------------------------------------------------------------------------
enum { MODE_SC = 2, MODE_PV = 3, MODE_FIN = 4 };

template <int MODE>
__global__ __launch_bounds__(NTH, 2)
void hgemm(const __half* __restrict__ A0, const __half* __restrict__ B,
           void* __restrict__ out, const float* __restrict__ X,
           float* __restrict__ RS,
           int ldA, int ldB, int ldC, int K,
           long long sAhi, long long sAlo, long long sBhi, long long sBlo,
           long long sChi, long long sClo, long long sXlo)
{
    extern __shared__ __align__(16) char smem[];
    const uint32_t sbase = s2u(smem);
    const int tid  = threadIdx.x;
    const int lane = tid & 31;
    const int warp = tid >> 5;
    const int wm = warp & 1;
    const int wn = warp >> 1;
    const int z  = blockIdx.z;
    const int zh = z >> 3, zl = z & 7;
    const int m0 = blockIdx.y * TM;
    const int n0 = blockIdx.x * TN;

    const __half* Ap = A0 + zh * sAhi + zl * sAlo;
    const __half* Bp = B + zh * sBhi + zl * sBlo;
    const size_t  co = (size_t)(zh * sChi + zl * sClo);

    GEMM_MAINLOOP(Ap, Bp, ldA, ldB, K)

    const int lm = lane >> 2;
    const int ln = (lane & 3) * 2;

    const __half2 clamp15 = __float2half2_rn(15.f);

    #pragma unroll
    for (int im = 0; im < 4; im++) {
        int r0 = m0 + wm * 64 + im * 16 + lm;
        int r1 = r0 + 8;
        float s0 = 0.f, s1 = 0.f;
        float inv0, inv1;
        if (MODE == MODE_PV) {
            inv0 = 1.0f / RS[(size_t)z * SEQ + r0];
            inv1 = 1.0f / RS[(size_t)z * SEQ + r1];
        }
        #pragma unroll
        for (int jn = 0; jn < 8; jn++) {
            int c = n0 + wn * 64 + jn * 8 + ln;
            float v0 = acc[im][jn][0], v1 = acc[im][jn][1];
            float v2 = acc[im][jn][2], v3 = acc[im][jn][3];
            if (MODE == MODE_SC) {
                __half* O = (__half*)out + co;
                __half2 p01 = h2exp2(__hmin2(__floats2half2_rn(v0, v1), clamp15));
                __half2 p23 = h2exp2(__hmin2(__floats2half2_rn(v2, v3), clamp15));
                *(__half2*)(O + (size_t)r0 * ldC + c) = p01;
                *(__half2*)(O + (size_t)r1 * ldC + c) = p23;
                float2 f0 = __half22float2(p01), f1 = __half22float2(p23);
                s0 += f0.x + f0.y;
                s1 += f1.x + f1.y;
            } else if (MODE == MODE_PV) {
                __half* O = (__half*)out + co;
                *(__half2*)(O + (size_t)r0 * ldC + c) = __floats2half2_rn(v0 * inv0, v1 * inv0);
                *(__half2*)(O + (size_t)r1 * ldC + c) = __floats2half2_rn(v2 * inv1, v3 * inv1);
            } else {  // MODE_FIN
                float* O = (float*)out + co;
                const float* Xz = X + zl * sXlo;
                size_t o0 = (size_t)r0 * ldC + c, o1 = (size_t)r1 * ldC + c;
                float2 p0 = *(const float2*)(Xz + o0), p1 = *(const float2*)(Xz + o1);
                *(float2*)(O + o0) = make_float2(v0 + p0.x, v1 + p0.y);
                *(float2*)(O + o1) = make_float2(v2 + p1.x, v3 + p1.y);
            }
        }
        if (MODE == MODE_SC) {
            s0 += __shfl_xor_sync(0xffffffffu, s0, 1);
            s0 += __shfl_xor_sync(0xffffffffu, s0, 2);
            s1 += __shfl_xor_sync(0xffffffffu, s1, 1);
            s1 += __shfl_xor_sync(0xffffffffu, s1, 2);
            if ((lane & 3) == 0) {
                atomicAdd(RS + (size_t)z * SEQ + r0, s0);
                atomicAdd(RS + (size_t)z * SEQ + r1, s1);
            }
        }
    }
}

// ---------------------------------------------------------------------------
// Fused fp32 -> fp16 convert of all 5 inputs + zero RS
// ---------------------------------------------------------------------------
#define N4_IN (MTOT * DD / 4)        // 2097152
#define N4_W  (4 * DD * DD / 4)      // 262144
#define N4_RS (32 * SEQ / 4)         // 16384
__global__ __launch_bounds__(256)
void convert_all(const float* __restrict__ IT, const float* __restrict__ IS,
                 const float* __restrict__ Wq, const float* __restrict__ Wk,
                 const float* __restrict__ Wv,
                 __half* __restrict__ oIT, __half* __restrict__ oIS,
                 __half* __restrict__ oWq, __half* __restrict__ oWk,
                 __half* __restrict__ oWv, float* __restrict__ RS)
{
    const int total = 2 * N4_IN + 3 * N4_W + N4_RS;
    int idx = blockIdx.x * blockDim.x + threadIdx.x;
    int stride = gridDim.x * blockDim.x;
    for (int i = idx; i < total; i += stride) {
        if (i >= 2 * N4_IN + 3 * N4_W) {
            ((float4*)RS)[i - 2 * N4_IN - 3 * N4_W] = make_float4(0.f, 0.f, 0.f, 0.f);
            continue;
        }
        const float4* s; __half2* d; int off;
        if (i < N4_IN)                     { s = (const float4*)IT; d = (__half2*)oIT; off = i; }
        else if (i < 2 * N4_IN)            { s = (const float4*)IS; d = (__half2*)oIS; off = i - N4_IN; }
        else if (i < 2 * N4_IN + N4_W)     { s = (const float4*)Wq; d = (__half2*)oWq; off = i - 2 * N4_IN; }
        else if (i < 2 * N4_IN + 2 * N4_W) { s = (const float4*)Wk; d = (__half2*)oWk; off = i - 2 * N4_IN - N4_W; }
        else                               { s = (const float4*)Wv; d = (__half2*)oWv; off = i - 2 * N4_IN - 2 * N4_W; }
        float4 v = s[off];
        d[off * 2]     = __floats2half2_rn(v.x, v.y);
        d[off * 2 + 1] = __floats2half2_rn(v.z, v.w);
    }
}

// ---------------------------------------------------------------------------
// Ah = F[0] + F[2]  (FTT + FTS),   Ch = F[1] + F[3]  (FSS + FST)
// ---------------------------------------------------------------------------
__global__ __launch_bounds__(256)
void fuse_kernel(const __half* __restrict__ F, __half* __restrict__ Ah,
                 __half* __restrict__ Ch, int n8)
{
    const size_t blk = (size_t)MTOT * DD;
    int idx = blockIdx.x * blockDim.x + threadIdx.x;
    int stride = gridDim.x * blockDim.x;
    const uint4* fTT = (const uint4*)F;
    const uint4* fSS = (const uint4*)(F + blk);
    const uint4* fTS = (const uint4*)(F + 2 * blk);
    const uint4* fST = (const uint4*)(F + 3 * blk);
    uint4* a4 = (uint4*)Ah;
    uint4* c4 = (uint4*)Ch;
    for (int i = idx; i < n8; i += stride) {
        uint4 x = fTT[i], y = fTS[i], r;
        ((__half2*)&r)[0] = __hadd2(((__half2*)&x)[0], ((__half2*)&y)[0]);
        ((__half2*)&r)[1] = __hadd2(((__half2*)&x)[1], ((__half2*)&y)[1]);
        ((__half2*)&r)[2] = __hadd2(((__half2*)&x)[2], ((__half2*)&y)[2]);
        ((__half2*)&r)[3] = __hadd2(((__half2*)&x)[3], ((__half2*)&y)[3]);
        a4[i] = r;
        x = fSS[i]; y = fST[i];
        ((__half2*)&r)[0] = __hadd2(((__half2*)&x)[0], ((__half2*)&y)[0]);
        ((__half2*)&r)[1] = __hadd2(((__half2*)&x)[1], ((__half2*)&y)[1]);
        ((__half2*)&r)[2] = __hadd2(((__half2*)&x)[2], ((__half2*)&y)[2]);
        ((__half2*)&r)[3] = __hadd2(((__half2*)&x)[3], ((__half2*)&y)[3]);
        c4[i] = r;
    }
}

// ---------------------------------------------------------------------------
extern "C" void kernel_launch(void* const* d_in, const int* in_sizes, int n_in,
                              void* d_out, int out_size)
{
    const float* Itime   = (const float*)d_in[0];
    const float* Ispace  = (const float*)d_in[1];
    const float* xorigin = (const float*)d_in[2];
    const float* Wq      = (const float*)d_in[3];
    const float* bq      = (const float*)d_in[4];
    const float* Wk      = (const float*)d_in[5];
    const float* bk      = (const float*)d_in[6];
    const float* Wv      = (const float*)d_in[7];
    const float* bv      = (const float*)d_in[8];
    float* out = (float*)d_out;

    __half *ITh, *ISh, *Wh, *Qh, *Kh, *Vth, *Sh, *Fh, *Ah, *Ch;
    float *RS;
    cudaGetSymbolAddress((void**)&ITh, g_ITh);
    cudaGetSymbolAddress((void**)&ISh, g_ISh);
    cudaGetSymbolAddress((void**)&Wh,  g_Wh);
    cudaGetSymbolAddress((void**)&Qh,  g_Qh);
    cudaGetSymbolAddress((void**)&Kh,  g_Kh);
    cudaGetSymbolAddress((void**)&Vth, g_Vth);
    cudaGetSymbolAddress((void**)&Sh,  g_S);
    cudaGetSymbolAddress((void**)&RS,  g_RS);
    cudaGetSymbolAddress((void**)&Fh,  g_F);
    cudaGetSymbolAddress((void**)&Ah,  g_Ah);
    cudaGetSymbolAddress((void**)&Ch,  g_Ch);

    cudaFuncSetAttribute(proj_kernel,     cudaFuncAttributeMaxDynamicSharedMemorySize, SMEM_TOTAL);
    cudaFuncSetAttribute(hgemm<MODE_SC>,  cudaFuncAttributeMaxDynamicSharedMemorySize, SMEM_TOTAL);
    cudaFuncSetAttribute(hgemm<MODE_PV>,  cudaFuncAttributeMaxDynamicSharedMemorySize, SMEM_TOTAL);
    cudaFuncSetAttribute(hgemm<MODE_FIN>, cudaFuncAttributeMaxDynamicSharedMemorySize, SMEM_TOTAL);

    const long long sQKV = (long long)SEQ * DD;
    const long long sBUF = (long long)MTOT * DD;
    const long long sS   = (long long)SEQ * SEQ;

    convert_all<<<4096, 256>>>(Itime, Ispace, Wq, Wk, Wv,
                               ITh, ISh, Wh, Wh + 4 * DD * DD, Wh + 8 * DD * DD, RS);

    dim3 gproj(DD / TN, MTOT / TM, 12);
    proj_kernel<<<gproj, NTH, SMEM_TOTAL>>>(ITh, ISh, Wh, bq, bk, bv, Qh, Kh, Vth);

    // Scores + exp2 + rowsum atomics (Q pre-scaled; normalization deferred)
    dim3 gsc(SEQ / TN, SEQ / TM, 32);
    hgemm<MODE_SC><<<gsc, NTH, SMEM_TOTAL>>>(
        Qh, Kh, Sh, nullptr, RS,
        DD, DD, SEQ, DD,
        8 * sQKV, sQKV, 8 * sQKV, sQKV, 8 * sS, sS, 0);

    // PV: normalize + plain fp16 stores into F
    dim3 gpv(DD / TN, SEQ / TM, 32);
    hgemm<MODE_PV><<<gpv, NTH, SMEM_TOTAL>>>(
        Sh, Vth, Fh, nullptr, RS,
        SEQ, MTOT, DD, SEQ,
        8 * sS, sS, sBUF, SEQ, 8 * sQKV, sQKV, 0);

    // Ah = FTT + FTS, Ch = FSS + FST
    fuse_kernel<<<1024, 256>>>(Fh, Ah, Ch, MTOT * DD / 8);

    // out[z] = A[z] @ C[z]^T + x_origin[z]
    dim3 gfin(SEQ / TN, SEQ / TM, BATCH);
    hgemm<MODE_FIN><<<gfin, NTH, SMEM_TOTAL>>>(
        Ah, Ch, out, xorigin, nullptr,
        DD, DD, SEQ, DD,
        0, sQKV, 0, sQKV, 0, sS, sS);
}

// round 14
// speedup vs baseline: 1.0462x; 1.0384x over previous
#include <cuda_runtime.h>
#include <cuda_fp16.h>
#include <stdint.h>
#include <math.h>

#define DD 512
#define BATCH 8
#define SEQ 2048
#define MTOT (BATCH * SEQ)   // 16384

#define TM 128
#define TN 128
#define BKK 64
#define NTH 128              // 4 warps: 2m x 2n, warp tile 64x64

#define STG_BYTES 32768
#define NSTG 3
#define SMEM_TOTAL (NSTG * STG_BYTES)   // 98304; 2 CTAs/SM

// scale(1/sqrt(512)) * log2(e): Q pre-scaled so SC acc is log2 of exp argument
#define QSCALE 0.06375871588f

// ---------------- scratch (device globals; no allocation) ----------------
__device__ __align__(1024) __half g_ITh[MTOT * DD];
__device__ __align__(1024) __half g_ISh[MTOT * DD];
__device__ __align__(1024) __half g_Wh[12 * DD * DD];                     // [Q0..3|K0..3|V0..3]
__device__ __align__(1024) __half g_Qh[4 * MTOT * DD];
__device__ __align__(1024) __half g_Kh[4 * MTOT * DD];
__device__ __align__(1024) __half g_Vth[4 * DD * MTOT];                   // [blk][feat][tok]
__device__ __align__(1024) __half g_S[(size_t)32 * SEQ * SEQ];            // unnormalized exp
__device__ __align__(1024) float  g_RS[32 * SEQ];                         // row sums
__device__ __align__(1024) __half g_F[(size_t)4 * MTOT * DD];
__device__ __align__(1024) __half g_Ah[MTOT * DD];
__device__ __align__(1024) __half g_Ch[MTOT * DD];

// ---------------- helpers ----------------
__device__ __forceinline__ uint32_t s2u(const void* p) {
    uint32_t a;
    asm("{ .reg .u64 t; cvta.to.shared.u64 t, %1; cvt.u32.u64 %0, t; }" : "=r"(a) : "l"(p));
    return a;
}
__device__ __forceinline__ void cp16(uint32_t dst, const void* src) {
    asm volatile("cp.async.cg.shared.global [%0], [%1], 16;" :: "r"(dst), "l"(src));
}
__device__ __forceinline__ void cp_commit() { asm volatile("cp.async.commit_group;" ::: "memory"); }
template <int N> __device__ __forceinline__ void cp_wait() {
    asm volatile("cp.async.wait_group %0;" :: "n"(N) : "memory");
}
__device__ __forceinline__ void ldsm4(uint32_t* d, uint32_t addr) {
    asm volatile("ldmatrix.sync.aligned.m8n8.x4.shared.b16 {%0,%1,%2,%3}, [%4];"
                 : "=r"(d[0]), "=r"(d[1]), "=r"(d[2]), "=r"(d[3]) : "r"(addr));
}
__device__ __forceinline__ void mma16816(float* c, const uint32_t* a, uint32_t b0, uint32_t b1) {
    asm volatile(
        "mma.sync.aligned.m16n8k16.row.col.f32.f16.f16.f32 "
        "{%0,%1,%2,%3},{%4,%5,%6,%7},{%8,%9},{%0,%1,%2,%3};"
        : "+f"(c[0]), "+f"(c[1]), "+f"(c[2]), "+f"(c[3])
        : "r"(a[0]), "r"(a[1]), "r"(a[2]), "r"(a[3]), "r"(b0), "r"(b1));
}

// =============== shared mainloop (CTA 128x128, 4 warps, 64x64 warp tile) ====
// Chunk-head software pipeline: s=0 LDSMs issue right after the barrier; the
// next-chunk cp.async burst issues while those LDSMs are in flight; s=0 MMAs
// then consume. Hides first-fragment latency under load-issue time.
#define GEMM_MAINLOOP(Ap, Bp, ldA, ldB, K)                                        \
    float acc[4][8][4];                                                           \
    _Pragma("unroll")                                                             \
    for (int i = 0; i < 4; i++)                                                   \
        _Pragma("unroll")                                                         \
        for (int j = 0; j < 8; j++)                                               \
            _Pragma("unroll")                                                     \
            for (int e = 0; e < 4; e++) acc[i][j][e] = 0.f;                       \
    const int nK = (K) / BKK;                                                     \
    auto load_stage = [&](int ck, int stg) {                                      \
        const int k0 = ck * BKK;                                                  \
        const uint32_t sb = sbase + stg * STG_BYTES;                              \
        _Pragma("unroll")                                                         \
        for (int t = 0; t < 8; t++) {                                             \
            int id = tid + t * NTH;                                               \
            int r = id >> 3, c = id & 7;                                          \
            cp16(sb + r * 128 + (((c ^ (r & 7)) & 7) << 4),                       \
                 (Ap) + (size_t)(m0 + r) * (ldA) + k0 + c * 8);                   \
        }                                                                         \
        _Pragma("unroll")                                                         \
        for (int t = 0; t < 8; t++) {                                             \
            int id = tid + t * NTH;                                               \
            int r = id >> 3, c = id & 7;                                          \
            cp16(sb + 16384 + r * 128 + (((c ^ (r & 7)) & 7) << 4),               \
                 (Bp) + (size_t)(n0 + r) * (ldB) + k0 + c * 8);                   \
        }                                                                         \
        cp_commit();                                                              \
    };                                                                            \
    load_stage(0, 0);                                                             \
    if (nK > 1) load_stage(1, 1);                                                 \
    for (int i = 0; i < nK; i++) {                                                \
        if (i + 1 < nK) cp_wait<1>(); else cp_wait<0>();                          \
        __syncthreads();                                                          \
        const uint32_t sA = sbase + (i % 3) * STG_BYTES;                          \
        const uint32_t sB = sA + 16384;                                           \
        uint32_t af[4][4], bf[4][4];                                              \
        /* s=0 fragment loads first (latency overlapped with cp16 burst) */       \
        _Pragma("unroll")                                                         \
        for (int im = 0; im < 4; im++) {                                          \
            int row = wm * 64 + im * 16 + (lane & 15);                            \
            int ch  = (lane >> 4);                                                \
            ldsm4(af[im], sA + row * 128 + (((ch ^ (row & 7)) & 7) << 4));        \
        }                                                                         \
        _Pragma("unroll")                                                         \
        for (int j2 = 0; j2 < 4; j2++) {                                          \
            int row = wn * 64 + j2 * 16 + ((lane >> 4) << 3) + (lane & 7);        \
            int ch  = ((lane >> 3) & 1);                                          \
            ldsm4(bf[j2], sB + row * 128 + (((ch ^ (row & 7)) & 7) << 4));        \
        }                                                                         \
        if (i + 2 < nK) load_stage(i + 2, (i + 2) % 3);                           \
        _Pragma("unroll")                                                         \
        for (int im = 0; im < 4; im++)                                            \
            _Pragma("unroll")                                                     \
            for (int jn = 0; jn < 8; jn++)                                        \
                mma16816(acc[im][jn], af[im], bf[jn >> 1][(jn & 1) * 2],          \
                         bf[jn >> 1][(jn & 1) * 2 + 1]);                          \
        _Pragma("unroll")                                                         \
        for (int s = 1; s < 4; s++) {                                             \
            _Pragma("unroll")                                                     \
            for (int im = 0; im < 4; im++) {                                      \
                int row = wm * 64 + im * 16 + (lane & 15);                        \
                int ch  = 2 * s + (lane >> 4);                                    \
                ldsm4(af[im], sA + row * 128 + (((ch ^ (row & 7)) & 7) << 4));    \
            }                                                                     \
            _Pragma("unroll")                                                     \
            for (int j2 = 0; j2 < 4; j2++) {                                      \
                int row = wn * 64 + j2 * 16 + ((lane >> 4) << 3) + (lane & 7);    \
                int ch  = 2 * s + ((lane >> 3) & 1);                              \
                ldsm4(bf[j2], sB + row * 128 + (((ch ^ (row & 7)) & 7) << 4));    \
            }                                                                     \
            _Pragma("unroll")                                                     \
            for (int im = 0; im < 4; im++)                                        \
                _Pragma("unroll")                                                 \
                for (int jn = 0; jn < 8; jn++)                                    \
                    mma16816(acc[im][jn], af[im], bf[jn >> 1][(jn & 1) * 2],      \
                             bf[jn >> 1][(jn & 1) * 2 + 1]);                      \
        }                                                                         \
    }

// ---------------------------------------------------------------------------
// Merged projection kernel: z = proj*4 + blk  (proj: 0=Q, 1=K, 2=V)
// Q output is pre-scaled by QSCALE so scores acc = log2(exp argument).
// ---------------------------------------------------------------------------
__global__ __launch_bounds__(NTH, 2)
void proj_kernel(const __half* __restrict__ IT, const __half* __restrict__ IS,
                 const __half* __restrict__ Wall,
                 const float* __restrict__ bq, const float* __restrict__ bk,
                 const float* __restrict__ bv,
                 __half* __restrict__ Qh, __half* __restrict__ Kh,
                 __half* __restrict__ Vth)
{
    extern __shared__ __align__(16) char smem[];
    const uint32_t sbase = s2u(smem);
    const int tid  = threadIdx.x;
    const int lane = tid & 31;
    const int warp = tid >> 5;
    const int wm = warp & 1;
    const int wn = warp >> 1;
    const int z  = blockIdx.z;
    const int proj = z >> 2;
    const int blk  = z & 3;
    const int m0 = blockIdx.y * TM;
    const int n0 = blockIdx.x * TN;
    const long long sBUF = (long long)MTOT * DD;

    const __half* Ap = (((0x66Au >> z) & 1) ? IS : IT);
    const __half* Bp = Wall + (size_t)z * DD * DD;
    const float*  Xp = (proj == 0 ? bq : proj == 1 ? bk : bv) + blk * DD;

    GEMM_MAINLOOP(Ap, Bp, DD, DD, DD)

    const int lm = lane >> 2;
    const int ln = (lane & 3) * 2;

    if (proj == 2) {
        __syncthreads();
        __half* st = (__half*)smem;
        #pragma unroll
        for (int im = 0; im < 4; im++) {
            int ml = wm * 64 + im * 16 + lm;
            #pragma unroll
            for (int jn = 0; jn < 8; jn++) {
                int nl = wn * 64 + jn * 8 + ln;
                float b0 = Xp[n0 + nl], b1 = Xp[n0 + nl + 1];
                st[nl * 136 + ml]           = __float2half(acc[im][jn][0] + b0);
                st[(nl + 1) * 136 + ml]     = __float2half(acc[im][jn][1] + b1);
                st[nl * 136 + ml + 8]       = __float2half(acc[im][jn][2] + b0);
                st[(nl + 1) * 136 + ml + 8] = __float2half(acc[im][jn][3] + b1);
            }
        }
        __syncthreads();
        __half* O = Vth + (size_t)blk * sBUF;
        #pragma unroll
        for (int t = 0; t < 16; t++) {
            int idx = tid + t * NTH;
            int r = idx >> 4, sgl = idx & 15;
            uint4 v = *(const uint4*)(st + r * 136 + sgl * 8);
            *(uint4*)(O + (size_t)(n0 + r) * MTOT + m0 + sgl * 8) = v;
        }
        return;
    }

    const float qs = (proj == 0) ? QSCALE : 1.0f;
    __half* O = (proj == 0 ? Qh : Kh) + (size_t)blk * sBUF;
    #pragma unroll
    for (int im = 0; im < 4; im++) {
        int r0 = m0 + wm * 64 + im * 16 + lm;
        int r1 = r0 + 8;
        #pragma unroll
        for (int jn = 0; jn < 8; jn++) {
            int c = n0 + wn * 64 + jn * 8 + ln;
            float b0 = Xp[c], b1 = Xp[c + 1];
            *(__half2*)(O + (size_t)r0 * DD + c) =
                __floats2half2_rn((acc[im][jn][0] + b0) * qs, (acc[im][jn][1] + b1) * qs);
            *(__half2*)(O + (size_t)r1 * DD + c) =
                __floats2half2_rn((acc[im][jn][2] + b0) * qs, (acc[im][jn][3] + b1) * qs);
        }
    }
}

// ---------------------------------------------------------------------------
// Generic NT GEMM (scores / PV / final), z-batched
// MODE_SC: P = exp2(acc) via h2exp2 (Q pre-scaled), rowsum atomics into RS
// MODE_PV: multiplies by 1/RS[row], plain fp16 stores into F
// ---------------------------------------------------------------------------
enum { MODE_SC = 2, MODE_PV = 3, MODE_FIN = 4 };

template <int MODE>
__global__ __launch_bounds__(NTH, 2)
void hgemm(const __half* __restrict__ A0, const __half* __restrict__ B,
           void* __restrict__ out, const float* __restrict__ X,
           float* __restrict__ RS,
           int ldA, int ldB, int ldC, int K,
           long long sAhi, long long sAlo, long long sBhi, long long sBlo,
           long long sChi, long long sClo, long long sXlo)
{
    extern __shared__ __align__(16) char smem[];
    const uint32_t sbase = s2u(smem);
    const int tid  = threadIdx.x;
    const int lane = tid & 31;
    const int warp = tid >> 5;
    const int wm = warp & 1;
    const int wn = warp >> 1;
    const int z  = blockIdx.z;
    const int zh = z >> 3, zl = z & 7;
    const int m0 = blockIdx.y * TM;
    const int n0 = blockIdx.x * TN;

    const __half* Ap = A0 + zh * sAhi + zl * sAlo;
    const __half* Bp = B + zh * sBhi + zl * sBlo;
    const size_t  co = (size_t)(zh * sChi + zl * sClo);

    GEMM_MAINLOOP(Ap, Bp, ldA, ldB, K)

    const int lm = lane >> 2;
    const int ln = (lane & 3) * 2;

    const __half2 clamp15 = __float2half2_rn(15.f);

    #pragma unroll
    for (int im = 0; im < 4; im++) {
        int r0 = m0 + wm * 64 + im * 16 + lm;
        int r1 = r0 + 8;
        float s0 = 0.f, s1 = 0.f;
        float inv0, inv1;
        if (MODE == MODE_PV) {
            inv0 = 1.0f / RS[(size_t)z * SEQ + r0];
            inv1 = 1.0f / RS[(size_t)z * SEQ + r1];
        }
        #pragma unroll
        for (int jn = 0; jn < 8; jn++) {
            int c = n0 + wn * 64 + jn * 8 + ln;
            float v0 = acc[im][jn][0], v1 = acc[im][jn][1];
            float v2 = acc[im][jn][2], v3 = acc[im][jn][3];
            if (MODE == MODE_SC) {
                __half* O = (__half*)out + co;
                __half2 p01 = h2exp2(__hmin2(__floats2half2_rn(v0, v1), clamp15));
                __half2 p23 = h2exp2(__hmin2(__floats2half2_rn(v2, v3), clamp15));
                *(__half2*)(O + (size_t)r0 * ldC + c) = p01;
                *(__half2*)(O + (size_t)r1 * ldC + c) = p23;
                float2 f0 = __half22float2(p01), f1 = __half22float2(p23);
                s0 += f0.x + f0.y;
                s1 += f1.x + f1.y;
            } else if (MODE == MODE_PV) {
                __half* O = (__half*)out + co;
                *(__half2*)(O + (size_t)r0 * ldC + c) = __floats2half2_rn(v0 * inv0, v1 * inv0);
                *(__half2*)(O + (size_t)r1 * ldC + c) = __floats2half2_rn(v2 * inv1, v3 * inv1);
            } else {  // MODE_FIN
                float* O = (float*)out + co;
                const float* Xz = X + zl * sXlo;
                size_t o0 = (size_t)r0 * ldC + c, o1 = (size_t)r1 * ldC + c;
                float2 p0 = *(const float2*)(Xz + o0), p1 = *(const float2*)(Xz + o1);
                *(float2*)(O + o0) = make_float2(v0 + p0.x, v1 + p0.y);
                *(float2*)(O + o1) = make_float2(v2 + p1.x, v3 + p1.y);
            }
        }
        if (MODE == MODE_SC) {
            s0 += __shfl_xor_sync(0xffffffffu, s0, 1);
            s0 += __shfl_xor_sync(0xffffffffu, s0, 2);
            s1 += __shfl_xor_sync(0xffffffffu, s1, 1);
            s1 += __shfl_xor_sync(0xffffffffu, s1, 2);
            if ((lane & 3) == 0) {
                atomicAdd(RS + (size_t)z * SEQ + r0, s0);
                atomicAdd(RS + (size_t)z * SEQ + r1, s1);
            }
        }
    }
}

// ---------------------------------------------------------------------------
// Fused fp32 -> fp16 convert of all 5 inputs + zero RS
// ---------------------------------------------------------------------------
#define N4_IN (MTOT * DD / 4)        // 2097152
#define N4_W  (4 * DD * DD / 4)      // 262144
#define N4_RS (32 * SEQ / 4)         // 16384
__global__ __launch_bounds__(256)
void convert_all(const float* __restrict__ IT, const float* __restrict__ IS,
                 const float* __restrict__ Wq, const float* __restrict__ Wk,
                 const float* __restrict__ Wv,
                 __half* __restrict__ oIT, __half* __restrict__ oIS,
                 __half* __restrict__ oWq, __half* __restrict__ oWk,
                 __half* __restrict__ oWv, float* __restrict__ RS)
{
    const int total = 2 * N4_IN + 3 * N4_W + N4_RS;
    int idx = blockIdx.x * blockDim.x + threadIdx.x;
    int stride = gridDim.x * blockDim.x;
    for (int i = idx; i < total; i += stride) {
        if (i >= 2 * N4_IN + 3 * N4_W) {
            ((float4*)RS)[i - 2 * N4_IN - 3 * N4_W] = make_float4(0.f, 0.f, 0.f, 0.f);
            continue;
        }
        const float4* s; __half2* d; int off;
        if (i < N4_IN)                     { s = (const float4*)IT; d = (__half2*)oIT; off = i; }
        else if (i < 2 * N4_IN)            { s = (const float4*)IS; d = (__half2*)oIS; off = i - N4_IN; }
        else if (i < 2 * N4_IN + N4_W)     { s = (const float4*)Wq; d = (__half2*)oWq; off = i - 2 * N4_IN; }
        else if (i < 2 * N4_IN + 2 * N4_W) { s = (const float4*)Wk; d = (__half2*)oWk; off = i - 2 * N4_IN - N4_W; }
        else                               { s = (const float4*)Wv; d = (__half2*)oWv; off = i - 2 * N4_IN - 2 * N4_W; }
        float4 v = s[off];
        d[off * 2]     = __floats2half2_rn(v.x, v.y);
        d[off * 2 + 1] = __floats2half2_rn(v.z, v.w);
    }
}

// ---------------------------------------------------------------------------
// Ah = F[0] + F[2]  (FTT + FTS),   Ch = F[1] + F[3]  (FSS + FST)
// ---------------------------------------------------------------------------
__global__ __launch_bounds__(256)
void fuse_kernel(const __half* __restrict__ F, __half* __restrict__ Ah,
                 __half* __restrict__ Ch, int n8)
{
    const size_t blk = (size_t)MTOT * DD;
    int idx = blockIdx.x * blockDim.x + threadIdx.x;
    int stride = gridDim.x * blockDim.x;
    const uint4* fTT = (const uint4*)F;
    const uint4* fSS = (const uint4*)(F + blk);
    const uint4* fTS = (const uint4*)(F + 2 * blk);
    const uint4* fST = (const uint4*)(F + 3 * blk);
    uint4* a4 = (uint4*)Ah;
    uint4* c4 = (uint4*)Ch;
    for (int i = idx; i < n8; i += stride) {
        uint4 x = fTT[i], y = fTS[i], r;
        ((__half2*)&r)[0] = __hadd2(((__half2*)&x)[0], ((__half2*)&y)[0]);
        ((__half2*)&r)[1] = __hadd2(((__half2*)&x)[1], ((__half2*)&y)[1]);
        ((__half2*)&r)[2] = __hadd2(((__half2*)&x)[2], ((__half2*)&y)[2]);
        ((__half2*)&r)[3] = __hadd2(((__half2*)&x)[3], ((__half2*)&y)[3]);
        a4[i] = r;
        x = fSS[i]; y = fST[i];
        ((__half2*)&r)[0] = __hadd2(((__half2*)&x)[0], ((__half2*)&y)[0]);
        ((__half2*)&r)[1] = __hadd2(((__half2*)&x)[1], ((__half2*)&y)[1]);
        ((__half2*)&r)[2] = __hadd2(((__half2*)&x)[2], ((__half2*)&y)[2]);
        ((__half2*)&r)[3] = __hadd2(((__half2*)&x)[3], ((__half2*)&y)[3]);
        c4[i] = r;
    }
}

// ---------------------------------------------------------------------------
extern "C" void kernel_launch(void* const* d_in, const int* in_sizes, int n_in,
                              void* d_out, int out_size)
{
    const float* Itime   = (const float*)d_in[0];
    const float* Ispace  = (const float*)d_in[1];
    const float* xorigin = (const float*)d_in[2];
    const float* Wq      = (const float*)d_in[3];
    const float* bq      = (const float*)d_in[4];
    const float* Wk      = (const float*)d_in[5];
    const float* bk      = (const float*)d_in[6];
    const float* Wv      = (const float*)d_in[7];
    const float* bv      = (const float*)d_in[8];
    float* out = (float*)d_out;

    __half *ITh, *ISh, *Wh, *Qh, *Kh, *Vth, *Sh, *Fh, *Ah, *Ch;
    float *RS;
    cudaGetSymbolAddress((void**)&ITh, g_ITh);
    cudaGetSymbolAddress((void**)&ISh, g_ISh);
    cudaGetSymbolAddress((void**)&Wh,  g_Wh);
    cudaGetSymbolAddress((void**)&Qh,  g_Qh);
    cudaGetSymbolAddress((void**)&Kh,  g_Kh);
    cudaGetSymbolAddress((void**)&Vth, g_Vth);
    cudaGetSymbolAddress((void**)&Sh,  g_S);
    cudaGetSymbolAddress((void**)&RS,  g_RS);
    cudaGetSymbolAddress((void**)&Fh,  g_F);
    cudaGetSymbolAddress((void**)&Ah,  g_Ah);
    cudaGetSymbolAddress((void**)&Ch,  g_Ch);

    cudaFuncSetAttribute(proj_kernel,     cudaFuncAttributeMaxDynamicSharedMemorySize, SMEM_TOTAL);
    cudaFuncSetAttribute(hgemm<MODE_SC>,  cudaFuncAttributeMaxDynamicSharedMemorySize, SMEM_TOTAL);
    cudaFuncSetAttribute(hgemm<MODE_PV>,  cudaFuncAttributeMaxDynamicSharedMemorySize, SMEM_TOTAL);
    cudaFuncSetAttribute(hgemm<MODE_FIN>, cudaFuncAttributeMaxDynamicSharedMemorySize, SMEM_TOTAL);

    const long long sQKV = (long long)SEQ * DD;
    const long long sBUF = (long long)MTOT * DD;
    const long long sS   = (long long)SEQ * SEQ;

    convert_all<<<4096, 256>>>(Itime, Ispace, Wq, Wk, Wv,
                               ITh, ISh, Wh, Wh + 4 * DD * DD, Wh + 8 * DD * DD, RS);

    dim3 gproj(DD / TN, MTOT / TM, 12);
    proj_kernel<<<gproj, NTH, SMEM_TOTAL>>>(ITh, ISh, Wh, bq, bk, bv, Qh, Kh, Vth);

    // Scores + exp2 + rowsum atomics (Q pre-scaled; normalization deferred)
    dim3 gsc(SEQ / TN, SEQ / TM, 32);
    hgemm<MODE_SC><<<gsc, NTH, SMEM_TOTAL>>>(
        Qh, Kh, Sh, nullptr, RS,
        DD, DD, SEQ, DD,
        8 * sQKV, sQKV, 8 * sQKV, sQKV, 8 * sS, sS, 0);

    // PV: normalize + plain fp16 stores into F
    dim3 gpv(DD / TN, SEQ / TM, 32);
    hgemm<MODE_PV><<<gpv, NTH, SMEM_TOTAL>>>(
        Sh, Vth, Fh, nullptr, RS,
        SEQ, MTOT, DD, SEQ,
        8 * sS, sS, sBUF, SEQ, 8 * sQKV, sQKV, 0);

    // Ah = FTT + FTS, Ch = FSS + FST
    fuse_kernel<<<1024, 256>>>(Fh, Ah, Ch, MTOT * DD / 8);

    // out[z] = A[z] @ C[z]^T + x_origin[z]
    dim3 gfin(SEQ / TN, SEQ / TM, BATCH);
    hgemm<MODE_FIN><<<gfin, NTH, SMEM_TOTAL>>>(
        Ah, Ch, out, xorigin, nullptr,
        DD, DD, SEQ, DD,
        0, sQKV, 0, sQKV, 0, sS, sS);
}

// round 15
// speedup vs baseline: 1.0940x; 1.0457x over previous
#include <cuda_runtime.h>
#include <cuda_fp16.h>
#include <stdint.h>
#include <math.h>

#define DD 512
#define BATCH 8
#define SEQ 2048
#define MTOT (BATCH * SEQ)   // 16384

#define TM 128
#define TN 128
#define BKK 64
#define NTH 128              // 4 warps: 2m x 2n, warp tile 64x64

#define STG_BYTES 32768
#define NSTG 3
#define SMEM_TOTAL (NSTG * STG_BYTES)   // 98304; 2 CTAs/SM

// scale(1/sqrt(512)) * log2(e): Q pre-scaled so SC acc is log2 of exp argument
#define QSCALE 0.06375871588f

// ---------------- scratch (device globals; no allocation) ----------------
__device__ __align__(1024) __half g_ITh[MTOT * DD];
__device__ __align__(1024) __half g_ISh[MTOT * DD];
__device__ __align__(1024) __half g_Wh[12 * DD * DD];                     // [Q0..3|K0..3|V0..3]
__device__ __align__(1024) __half g_Qh[4 * MTOT * DD];
__device__ __align__(1024) __half g_Kh[4 * MTOT * DD];
__device__ __align__(1024) __half g_Vth[4 * DD * MTOT];                   // [blk][feat][tok]
__device__ __align__(1024) __half g_S[(size_t)32 * SEQ * SEQ];            // unnormalized exp
__device__ __align__(1024) float  g_RS[32 * SEQ];                         // row sums
__device__ __align__(1024) __half g_F[(size_t)4 * MTOT * DD];
__device__ __align__(1024) __half g_Ah[MTOT * DD];
__device__ __align__(1024) __half g_Ch[MTOT * DD];

// ---------------- helpers ----------------
__device__ __forceinline__ uint32_t s2u(const void* p) {
    uint32_t a;
    asm("{ .reg .u64 t; cvta.to.shared.u64 t, %1; cvt.u32.u64 %0, t; }" : "=r"(a) : "l"(p));
    return a;
}
__device__ __forceinline__ void cp16(uint32_t dst, const void* src) {
    asm volatile("cp.async.cg.shared.global [%0], [%1], 16;" :: "r"(dst), "l"(src));
}
__device__ __forceinline__ void cp_commit() { asm volatile("cp.async.commit_group;" ::: "memory"); }
template <int N> __device__ __forceinline__ void cp_wait() {
    asm volatile("cp.async.wait_group %0;" :: "n"(N) : "memory");
}
__device__ __forceinline__ void ldsm4(uint32_t* d, uint32_t addr) {
    asm volatile("ldmatrix.sync.aligned.m8n8.x4.shared.b16 {%0,%1,%2,%3}, [%4];"
                 : "=r"(d[0]), "=r"(d[1]), "=r"(d[2]), "=r"(d[3]) : "r"(addr));
}
__device__ __forceinline__ void mma16816(float* c, const uint32_t* a, uint32_t b0, uint32_t b1) {
    asm volatile(
        "mma.sync.aligned.m16n8k16.row.col.f32.f16.f16.f32 "
        "{%0,%1,%2,%3},{%4,%5,%6,%7},{%8,%9},{%0,%1,%2,%3};"
        : "+f"(c[0]), "+f"(c[1]), "+f"(c[2]), "+f"(c[3])
        : "r"(a[0]), "r"(a[1]), "r"(a[2]), "r"(a[3]), "r"(b0), "r"(b1));
}

// 4x4 transpose of 32-bit values across a quad (lanes sharing lane>>2).
// Before: lane q holds x[i] = value for segment-slot i, sub-slot q.
// After:  lane q holds x[i] = the 4 contiguous values of segment-slot q.
__device__ __forceinline__ void quad_t4(uint32_t x[4], int q) {
    uint32_t t0, t1;
    // swap off-diagonal 2x2 blocks
    if (q & 2) { t0 = x[0]; t1 = x[1]; } else { t0 = x[2]; t1 = x[3]; }
    t0 = __shfl_xor_sync(0xffffffffu, t0, 2);
    t1 = __shfl_xor_sync(0xffffffffu, t1, 2);
    if (q & 2) { x[0] = t0; x[1] = t1; } else { x[2] = t0; x[3] = t1; }
    // transpose each 2x2 block
    if (q & 1) { t0 = x[0]; t1 = x[2]; } else { t0 = x[1]; t1 = x[3]; }
    t0 = __shfl_xor_sync(0xffffffffu, t0, 1);
    t1 = __shfl_xor_sync(0xffffffffu, t1, 1);
    if (q & 1) { x[0] = t0; x[2] = t1; } else { x[1] = t0; x[3] = t1; }
}

// Store 8 half2 row-fragment values (jn=0..7) as 2 x STG.128 per lane.
__device__ __forceinline__ void store_row16(uint32_t h[8], __half* rowbase, int colbase, int q) {
    #pragma unroll
    for (int b = 0; b < 2; b++) {
        uint32_t u[4] = { h[4 * b], h[4 * b + 1], h[4 * b + 2], h[4 * b + 3] };
        quad_t4(u, q);
        *(uint4*)(rowbase + colbase + (4 * b + q) * 8) = make_uint4(u[0], u[1], u[2], u[3]);
    }
}

// =============== shared mainloop (CTA 128x128, 4 warps, 64x64 warp tile) ====
// Chunk-head software pipeline: s=0 LDSMs issue right after the barrier; the
// next-chunk cp.async burst issues while those LDSMs are in flight; s=0 MMAs
// then consume.
#define GEMM_MAINLOOP(Ap, Bp, ldA, ldB, K)                                        \
    float acc[4][8][4];                                                           \
    _Pragma("unroll")                                                             \
    for (int i = 0; i < 4; i++)                                                   \
        _Pragma("unroll")                                                         \
        for (int j = 0; j < 8; j++)                                               \
            _Pragma("unroll")                                                     \
            for (int e = 0; e < 4; e++) acc[i][j][e] = 0.f;                       \
    const int nK = (K) / BKK;                                                     \
    auto load_stage = [&](int ck, int stg) {                                      \
        const int k0 = ck * BKK;                                                  \
        const uint32_t sb = sbase + stg * STG_BYTES;                              \
        _Pragma("unroll")                                                         \
        for (int t = 0; t < 8; t++) {                                             \
            int id = tid + t * NTH;                                               \
            int r = id >> 3, c = id & 7;                                          \
            cp16(sb + r * 128 + (((c ^ (r & 7)) & 7) << 4),                       \
                 (Ap) + (size_t)(m0 + r) * (ldA) + k0 + c * 8);                   \
        }                                                                         \
        _Pragma("unroll")                                                         \
        for (int t = 0; t < 8; t++) {                                             \
            int id = tid + t * NTH;                                               \
            int r = id >> 3, c = id & 7;                                          \
            cp16(sb + 16384 + r * 128 + (((c ^ (r & 7)) & 7) << 4),               \
                 (Bp) + (size_t)(n0 + r) * (ldB) + k0 + c * 8);                   \
        }                                                                         \
        cp_commit();                                                              \
    };                                                                            \
    load_stage(0, 0);                                                             \
    if (nK > 1) load_stage(1, 1);                                                 \
    for (int i = 0; i < nK; i++) {                                                \
        if (i + 1 < nK) cp_wait<1>(); else cp_wait<0>();                          \
        __syncthreads();                                                          \
        const uint32_t sA = sbase + (i % 3) * STG_BYTES;                          \
        const uint32_t sB = sA + 16384;                                           \
        uint32_t af[4][4], bf[4][4];                                              \
        _Pragma("unroll")                                                         \
        for (int im = 0; im < 4; im++) {                                          \
            int row = wm * 64 + im * 16 + (lane & 15);                            \
            int ch  = (lane >> 4);                                                \
            ldsm4(af[im], sA + row * 128 + (((ch ^ (row & 7)) & 7) << 4));        \
        }                                                                         \
        _Pragma("unroll")                                                         \
        for (int j2 = 0; j2 < 4; j2++) {                                          \
            int row = wn * 64 + j2 * 16 + ((lane >> 4) << 3) + (lane & 7);        \
            int ch  = ((lane >> 3) & 1);                                          \
            ldsm4(bf[j2], sB + row * 128 + (((ch ^ (row & 7)) & 7) << 4));        \
        }                                                                         \
        if (i + 2 < nK) load_stage(i + 2, (i + 2) % 3);                           \
        _Pragma("unroll")                                                         \
        for (int im = 0; im < 4; im++)                                            \
            _Pragma("unroll")                                                     \
            for (int jn = 0; jn < 8; jn++)                                        \
                mma16816(acc[im][jn], af[im], bf[jn >> 1][(jn & 1) * 2],          \
                         bf[jn >> 1][(jn & 1) * 2 + 1]);                          \
        _Pragma("unroll")                                                         \
        for (int s = 1; s < 4; s++) {                                             \
            _Pragma("unroll")                                                     \
            for (int im = 0; im < 4; im++) {                                      \
                int row = wm * 64 + im * 16 + (lane & 15);                        \
                int ch  = 2 * s + (lane >> 4);                                    \
                ldsm4(af[im], sA + row * 128 + (((ch ^ (row & 7)) & 7) << 4));    \
            }                                                                     \
            _Pragma("unroll")                                                     \
            for (int j2 = 0; j2 < 4; j2++) {                                      \
                int row = wn * 64 + j2 * 16 + ((lane >> 4) << 3) + (lane & 7);    \
                int ch  = 2 * s + ((lane >> 3) & 1);                              \
                ldsm4(bf[j2], sB + row * 128 + (((ch ^ (row & 7)) & 7) << 4));    \
            }                                                                     \
            _Pragma("unroll")                                                     \
            for (int im = 0; im < 4; im++)                                        \
                _Pragma("unroll")                                                 \
                for (int jn = 0; jn < 8; jn++)                                    \
                    mma16816(acc[im][jn], af[im], bf[jn >> 1][(jn & 1) * 2],      \
                             bf[jn >> 1][(jn & 1) * 2 + 1]);                      \
        }                                                                         \
    }

// ---------------------------------------------------------------------------
// Merged projection kernel: z = proj*4 + blk  (proj: 0=Q, 1=K, 2=V)
// Q output is pre-scaled by QSCALE so scores acc = log2(exp argument).
// ---------------------------------------------------------------------------
__global__ __launch_bounds__(NTH, 2)
void proj_kernel(const __half* __restrict__ IT, const __half* __restrict__ IS,
                 const __half* __restrict__ Wall,
                 const float* __restrict__ bq, const float* __restrict__ bk,
                 const float* __restrict__ bv,
                 __half* __restrict__ Qh, __half* __restrict__ Kh,
                 __half* __restrict__ Vth)
{
    extern __shared__ __align__(16) char smem[];
    const uint32_t sbase = s2u(smem);
    const int tid  = threadIdx.x;
    const int lane = tid & 31;
    const int warp = tid >> 5;
    const int wm = warp & 1;
    const int wn = warp >> 1;
    const int z  = blockIdx.z;
    const int proj = z >> 2;
    const int blk  = z & 3;
    const int m0 = blockIdx.y * TM;
    const int n0 = blockIdx.x * TN;
    const long long sBUF = (long long)MTOT * DD;

    const __half* Ap = (((0x66Au >> z) & 1) ? IS : IT);
    const __half* Bp = Wall + (size_t)z * DD * DD;
    const float*  Xp = (proj == 0 ? bq : proj == 1 ? bk : bv) + blk * DD;

    GEMM_MAINLOOP(Ap, Bp, DD, DD, DD)

    const int lm = lane >> 2;
    const int ln = (lane & 3) * 2;
    const int q  = lane & 3;

    if (proj == 2) {
        __syncthreads();
        __half* st = (__half*)smem;
        #pragma unroll
        for (int im = 0; im < 4; im++) {
            int ml = wm * 64 + im * 16 + lm;
            #pragma unroll
            for (int jn = 0; jn < 8; jn++) {
                int nl = wn * 64 + jn * 8 + ln;
                float b0 = Xp[n0 + nl], b1 = Xp[n0 + nl + 1];
                st[nl * 136 + ml]           = __float2half(acc[im][jn][0] + b0);
                st[(nl + 1) * 136 + ml]     = __float2half(acc[im][jn][1] + b1);
                st[nl * 136 + ml + 8]       = __float2half(acc[im][jn][2] + b0);
                st[(nl + 1) * 136 + ml + 8] = __float2half(acc[im][jn][3] + b1);
            }
        }
        __syncthreads();
        __half* O = Vth + (size_t)blk * sBUF;
        #pragma unroll
        for (int t = 0; t < 16; t++) {
            int idx = tid + t * NTH;
            int r = idx >> 4, sgl = idx & 15;
            uint4 v = *(const uint4*)(st + r * 136 + sgl * 8);
            *(uint4*)(O + (size_t)(n0 + r) * MTOT + m0 + sgl * 8) = v;
        }
        return;
    }

    const float qs = (proj == 0) ? QSCALE : 1.0f;
    __half* O = (proj == 0 ? Qh : Kh) + (size_t)blk * sBUF;
    const int colbase = n0 + wn * 64;
    #pragma unroll
    for (int im = 0; im < 4; im++) {
        int r0 = m0 + wm * 64 + im * 16 + lm;
        int r1 = r0 + 8;
        uint32_t h0[8], h1[8];
        #pragma unroll
        for (int jn = 0; jn < 8; jn++) {
            int c = colbase + jn * 8 + ln;
            float b0 = Xp[c], b1 = Xp[c + 1];
            __half2 a = __floats2half2_rn((acc[im][jn][0] + b0) * qs, (acc[im][jn][1] + b1) * qs);
            __half2 b = __floats2half2_rn((acc[im][jn][2] + b0) * qs, (acc[im][jn][3] + b1) * qs);
            h0[jn] = *(uint32_t*)&a;
            h1[jn] = *(uint32_t*)&b;
        }
        store_row16(h0, O + (size_t)r0 * DD, colbase, q);
        store_row16(h1, O + (size_t)r1 * DD, colbase, q);
    }
}

// ---------------------------------------------------------------------------
// Generic NT GEMM (scores / PV / final), z-batched
// MODE_SC: P = exp2(acc) via h2exp2 (Q pre-scaled), rowsum atomics into RS
// MODE_PV: multiplies by 1/RS[row], fp16 stores into F
// ---------------------------------------------------------------------------
enum { MODE_SC = 2, MODE_PV = 3, MODE_FIN = 4 };

template <int MODE>
__global__ __launch_bounds__(NTH, 2)
void hgemm(const __half* __restrict__ A0, const __half* __restrict__ B,
           void* __restrict__ out, const float* __restrict__ X,
           float* __restrict__ RS,
           int ldA, int ldB, int ldC, int K,
           long long sAhi, long long sAlo, long long sBhi, long long sBlo,
           long long sChi, long long sClo, long long sXlo)
{
    extern __shared__ __align__(16) char smem[];
    const uint32_t sbase = s2u(smem);
    const int tid  = threadIdx.x;
    const int lane = tid & 31;
    const int warp = tid >> 5;
    const int wm = warp & 1;
    const int wn = warp >> 1;
    const int z  = blockIdx.z;
    const int zh = z >> 3, zl = z & 7;
    const int m0 = blockIdx.y * TM;
    const int n0 = blockIdx.x * TN;

    const __half* Ap = A0 + zh * sAhi + zl * sAlo;
    const __half* Bp = B + zh * sBhi + zl * sBlo;
    const size_t  co = (size_t)(zh * sChi + zl * sClo);

    GEMM_MAINLOOP(Ap, Bp, ldA, ldB, K)

    const int lm = lane >> 2;
    const int ln = (lane & 3) * 2;
    const int q  = lane & 3;
    const int colbase = n0 + wn * 64;

    const __half2 clamp15 = __float2half2_rn(15.f);

    #pragma unroll
    for (int im = 0; im < 4; im++) {
        int r0 = m0 + wm * 64 + im * 16 + lm;
        int r1 = r0 + 8;
        if (MODE == MODE_SC) {
            __half* O = (__half*)out + co;
            uint32_t h0[8], h1[8];
            float s0 = 0.f, s1 = 0.f;
            #pragma unroll
            for (int jn = 0; jn < 8; jn++) {
                __half2 p01 = h2exp2(__hmin2(__floats2half2_rn(acc[im][jn][0], acc[im][jn][1]), clamp15));
                __half2 p23 = h2exp2(__hmin2(__floats2half2_rn(acc[im][jn][2], acc[im][jn][3]), clamp15));
                h0[jn] = *(uint32_t*)&p01;
                h1[jn] = *(uint32_t*)&p23;
                float2 f0 = __half22float2(p01), f1 = __half22float2(p23);
                s0 += f0.x + f0.y;
                s1 += f1.x + f1.y;
            }
            store_row16(h0, O + (size_t)r0 * ldC, colbase, q);
            store_row16(h1, O + (size_t)r1 * ldC, colbase, q);
            s0 += __shfl_xor_sync(0xffffffffu, s0, 1);
            s0 += __shfl_xor_sync(0xffffffffu, s0, 2);
            s1 += __shfl_xor_sync(0xffffffffu, s1, 1);
            s1 += __shfl_xor_sync(0xffffffffu, s1, 2);
            if (q == 0) {
                atomicAdd(RS + (size_t)z * SEQ + r0, s0);
                atomicAdd(RS + (size_t)z * SEQ + r1, s1);
            }
        } else if (MODE == MODE_PV) {
            __half* O = (__half*)out + co;
            float inv0 = 1.0f / RS[(size_t)z * SEQ + r0];
            float inv1 = 1.0f / RS[(size_t)z * SEQ + r1];
            uint32_t h0[8], h1[8];
            #pragma unroll
            for (int jn = 0; jn < 8; jn++) {
                __half2 a = __floats2half2_rn(acc[im][jn][0] * inv0, acc[im][jn][1] * inv0);
                __half2 b = __floats2half2_rn(acc[im][jn][2] * inv1, acc[im][jn][3] * inv1);
                h0[jn] = *(uint32_t*)&a;
                h1[jn] = *(uint32_t*)&b;
            }
            store_row16(h0, O + (size_t)r0 * ldC, colbase, q);
            store_row16(h1, O + (size_t)r1 * ldC, colbase, q);
        } else {  // MODE_FIN
            float* O = (float*)out + co;
            const float* Xz = X + zl * sXlo;
            #pragma unroll
            for (int jn = 0; jn < 8; jn++) {
                int c = colbase + jn * 8 + ln;
                size_t o0 = (size_t)r0 * ldC + c, o1 = (size_t)r1 * ldC + c;
                float2 p0 = *(const float2*)(Xz + o0), p1 = *(const float2*)(Xz + o1);
                *(float2*)(O + o0) = make_float2(acc[im][jn][0] + p0.x, acc[im][jn][1] + p0.y);
                *(float2*)(O + o1) = make_float2(acc[im][jn][2] + p1.x, acc[im][jn][3] + p1.y);
            }
        }
    }
}

// ---------------------------------------------------------------------------
// Fused fp32 -> fp16 convert of all 5 inputs + zero RS
// ---------------------------------------------------------------------------
#define N4_IN (MTOT * DD / 4)        // 2097152
#define N4_W  (4 * DD * DD / 4)      // 262144
#define N4_RS (32 * SEQ / 4)         // 16384
__global__ __launch_bounds__(256)
void convert_all(const float* __restrict__ IT, const float* __restrict__ IS,
                 const float* __restrict__ Wq, const float* __restrict__ Wk,
                 const float* __restrict__ Wv,
                 __half* __restrict__ oIT, __half* __restrict__ oIS,
                 __half* __restrict__ oWq, __half* __restrict__ oWk,
                 __half* __restrict__ oWv, float* __restrict__ RS)
{
    const int total = 2 * N4_IN + 3 * N4_W + N4_RS;
    int idx = blockIdx.x * blockDim.x + threadIdx.x;
    int stride = gridDim.x * blockDim.x;
    for (int i = idx; i < total; i += stride) {
        if (i >= 2 * N4_IN + 3 * N4_W) {
            ((float4*)RS)[i - 2 * N4_IN - 3 * N4_W] = make_float4(0.f, 0.f, 0.f, 0.f);
            continue;
        }
        const float4* s; __half2* d; int off;
        if (i < N4_IN)                     { s = (const float4*)IT; d = (__half2*)oIT; off = i; }
        else if (i < 2 * N4_IN)            { s = (const float4*)IS; d = (__half2*)oIS; off = i - N4_IN; }
        else if (i < 2 * N4_IN + N4_W)     { s = (const float4*)Wq; d = (__half2*)oWq; off = i - 2 * N4_IN; }
        else if (i < 2 * N4_IN + 2 * N4_W) { s = (const float4*)Wk; d = (__half2*)oWk; off = i - 2 * N4_IN - N4_W; }
        else                               { s = (const float4*)Wv; d = (__half2*)oWv; off = i - 2 * N4_IN - 2 * N4_W; }
        float4 v = s[off];
        d[off * 2]     = __floats2half2_rn(v.x, v.y);
        d[off * 2 + 1] = __floats2half2_rn(v.z, v.w);
    }
}

// ---------------------------------------------------------------------------
// Ah = F[0] + F[2]  (FTT + FTS),   Ch = F[1] + F[3]  (FSS + FST)
// ---------------------------------------------------------------------------
__global__ __launch_bounds__(256)
void fuse_kernel(const __half* __restrict__ F, __half* __restrict__ Ah,
                 __half* __restrict__ Ch, int n8)
{
    const size_t blk = (size_t)MTOT * DD;
    int idx = blockIdx.x * blockDim.x + threadIdx.x;
    int stride = gridDim.x * blockDim.x;
    const uint4* fTT = (const uint4*)F;
    const uint4* fSS = (const uint4*)(F + blk);
    const uint4* fTS = (const uint4*)(F + 2 * blk);
    const uint4* fST = (const uint4*)(F + 3 * blk);
    uint4* a4 = (uint4*)Ah;
    uint4* c4 = (uint4*)Ch;
    for (int i = idx; i < n8; i += stride) {
        uint4 x = fTT[i], y = fTS[i], r;
        ((__half2*)&r)[0] = __hadd2(((__half2*)&x)[0], ((__half2*)&y)[0]);
        ((__half2*)&r)[1] = __hadd2(((__half2*)&x)[1], ((__half2*)&y)[1]);
        ((__half2*)&r)[2] = __hadd2(((__half2*)&x)[2], ((__half2*)&y)[2]);
        ((__half2*)&r)[3] = __hadd2(((__half2*)&x)[3], ((__half2*)&y)[3]);
        a4[i] = r;
        x = fSS[i]; y = fST[i];
        ((__half2*)&r)[0] = __hadd2(((__half2*)&x)[0], ((__half2*)&y)[0]);
        ((__half2*)&r)[1] = __hadd2(((__half2*)&x)[1], ((__half2*)&y)[1]);
        ((__half2*)&r)[2] = __hadd2(((__half2*)&x)[2], ((__half2*)&y)[2]);
        ((__half2*)&r)[3] = __hadd2(((__half2*)&x)[3], ((__half2*)&y)[3]);
        c4[i] = r;
    }
}

// ---------------------------------------------------------------------------
extern "C" void kernel_launch(void* const* d_in, const int* in_sizes, int n_in,
                              void* d_out, int out_size)
{
    const float* Itime   = (const float*)d_in[0];
    const float* Ispace  = (const float*)d_in[1];
    const float* xorigin = (const float*)d_in[2];
    const float* Wq      = (const float*)d_in[3];
    const float* bq      = (const float*)d_in[4];
    const float* Wk      = (const float*)d_in[5];
    const float* bk      = (const float*)d_in[6];
    const float* Wv      = (const float*)d_in[7];
    const float* bv      = (const float*)d_in[8];
    float* out = (float*)d_out;

    __half *ITh, *ISh, *Wh, *Qh, *Kh, *Vth, *Sh, *Fh, *Ah, *Ch;
    float *RS;
    cudaGetSymbolAddress((void**)&ITh, g_ITh);
    cudaGetSymbolAddress((void**)&ISh, g_ISh);
    cudaGetSymbolAddress((void**)&Wh,  g_Wh);
    cudaGetSymbolAddress((void**)&Qh,  g_Qh);
    cudaGetSymbolAddress((void**)&Kh,  g_Kh);
    cudaGetSymbolAddress((void**)&Vth, g_Vth);
    cudaGetSymbolAddress((void**)&Sh,  g_S);
    cudaGetSymbolAddress((void**)&RS,  g_RS);
    cudaGetSymbolAddress((void**)&Fh,  g_F);
    cudaGetSymbolAddress((void**)&Ah,  g_Ah);
    cudaGetSymbolAddress((void**)&Ch,  g_Ch);

    cudaFuncSetAttribute(proj_kernel,     cudaFuncAttributeMaxDynamicSharedMemorySize, SMEM_TOTAL);
    cudaFuncSetAttribute(hgemm<MODE_SC>,  cudaFuncAttributeMaxDynamicSharedMemorySize, SMEM_TOTAL);
    cudaFuncSetAttribute(hgemm<MODE_PV>,  cudaFuncAttributeMaxDynamicSharedMemorySize, SMEM_TOTAL);
    cudaFuncSetAttribute(hgemm<MODE_FIN>, cudaFuncAttributeMaxDynamicSharedMemorySize, SMEM_TOTAL);

    const long long sQKV = (long long)SEQ * DD;
    const long long sBUF = (long long)MTOT * DD;
    const long long sS   = (long long)SEQ * SEQ;

    convert_all<<<4096, 256>>>(Itime, Ispace, Wq, Wk, Wv,
                               ITh, ISh, Wh, Wh + 4 * DD * DD, Wh + 8 * DD * DD, RS);

    dim3 gproj(DD / TN, MTOT / TM, 12);
    proj_kernel<<<gproj, NTH, SMEM_TOTAL>>>(ITh, ISh, Wh, bq, bk, bv, Qh, Kh, Vth);

    // Scores + exp2 + rowsum atomics (Q pre-scaled; normalization deferred)
    dim3 gsc(SEQ / TN, SEQ / TM, 32);
    hgemm<MODE_SC><<<gsc, NTH, SMEM_TOTAL>>>(
        Qh, Kh, Sh, nullptr, RS,
        DD, DD, SEQ, DD,
        8 * sQKV, sQKV, 8 * sQKV, sQKV, 8 * sS, sS, 0);

    // PV: normalize + fp16 stores into F
    dim3 gpv(DD / TN, SEQ / TM, 32);
    hgemm<MODE_PV><<<gpv, NTH, SMEM_TOTAL>>>(
        Sh, Vth, Fh, nullptr, RS,
        SEQ, MTOT, DD, SEQ,
        8 * sS, sS, sBUF, SEQ, 8 * sQKV, sQKV, 0);

    // Ah = FTT + FTS, Ch = FSS + FST
    fuse_kernel<<<2048, 256>>>(Fh, Ah, Ch, MTOT * DD / 8);

    // out[z] = A[z] @ C[z]^T + x_origin[z]
    dim3 gfin(SEQ / TN, SEQ / TM, BATCH);
    hgemm<MODE_FIN><<<gfin, NTH, SMEM_TOTAL>>>(
        Ah, Ch, out, xorigin, nullptr,
        DD, DD, SEQ, DD,
        0, sQKV, 0, sQKV, 0, sS, sS);
}